// round 14
// baseline (speedup 1.0000x reference)
#include <cuda_runtime.h>
#include <cuda_bf16.h>
#include <cstdint>
#include <cstddef>

// ---------------- problem constants ----------------
#define BSZ   64
#define SSZ   256
#define TSZ   32
#define VT    32000
#define BOS   2
#define NBLK  64
#define NSTEPS 289

// ---------------- device scratch (static; no allocs) ----------------
__device__ float4 g_pih_enc[(size_t)SSZ * 512 * BSZ]; // [t][j][b] (i,f,g,o)
__device__ float4 g_pih_dec[(size_t)TSZ * 512 * BSZ];

// Weights pre-packed in mma A-fragment order, bf16x2 words (layouts from R11).
__device__ __align__(128) uint32_t g_w0f[2][32][16384]; // [ph][c] 16 cells,K=512
__device__ __align__(128) uint32_t g_w1f[2][64][16384]; // [ph][c] 8 cells,K=1024

// h in mma B-fragment order: word ((kt*8+nt)*32+lane)*2+reg
__device__ __align__(128) uint32_t g_hf0[2][16384];     // h layer0, parity
__device__ __align__(128) uint32_t g_hf1[2][16384];     // h layer1, parity
__device__ float g_h1f[BSZ * 512];                      // fp32 h1(final) for FC

__device__ int g_tok_enc[SSZ * BSZ];
__device__ int g_tok_dec[TSZ * BSZ];

__device__ unsigned g_gcnt[8 * 32];
__device__ unsigned g_root[32];
__device__ unsigned g_gen[32];

// ---------------- helpers ----------------
__device__ __forceinline__ uint32_t smem_u32(const void* p) {
    uint32_t a;
    asm("{ .reg .u64 t; cvta.to.shared.u64 t, %1; cvt.u32.u64 %0, t; }"
        : "=r"(a) : "l"(p));
    return a;
}
__device__ __forceinline__ uint32_t elect_one() {
    uint32_t pred;
    asm volatile("{\n\t.reg .pred p;\n\telect.sync _|p, 0xFFFFFFFF;\n\t"
                 "selp.b32 %0, 1, 0, p;\n\t}" : "=r"(pred));
    return pred;
}
__device__ __forceinline__ float tanh_ap(float x) {
    float y;
    asm("tanh.approx.f32 %0, %1;" : "=f"(y) : "f"(x));
    return y;
}
__device__ __forceinline__ float sig_ap(float x) {
    return 0.5f * tanh_ap(0.5f * x) + 0.5f;
}

#define MBAR_INIT(a, n) \
    asm volatile("mbarrier.init.shared.b64 [%0], %1;" :: "r"(a), "r"(n) : "memory")
#define MBAR_EXPECT_TX(a, n) \
    asm volatile("mbarrier.arrive.expect_tx.shared.b64 _, [%0], %1;" \
                 :: "r"(a), "r"(n) : "memory")
#define MBAR_WAIT(a, ph) \
    asm volatile("{\n\t.reg .pred P1;\n\t" \
        "WL_%=:\n\t" \
        "mbarrier.try_wait.parity.acquire.cta.shared::cta.b64 P1, [%0], %1, 0x989680;\n\t" \
        "@P1 bra.uni WD_%=;\n\t" \
        "bra.uni WL_%=;\n\t" \
        "WD_%=:\n\t}" \
        :: "r"((uint32_t)(a)), "r"((uint32_t)(ph)) : "memory")

__device__ __forceinline__ void bulk_g2s(uint32_t dst, const void* src,
                                         uint32_t bytes, uint32_t mbar) {
    asm volatile(
        "cp.async.bulk.shared::cta.global.mbarrier::complete_tx::bytes [%0], [%1], %2, [%3];"
        :: "r"(dst), "l"(src), "r"(bytes), "r"(mbar) : "memory");
}

// bf16 mma: D[16x8] += A[16x16] * B[16x8], row.col, f32 accum
__device__ __forceinline__ void mma_bf16(float* d, const uint32_t* a, uint2 b) {
    asm volatile(
        "mma.sync.aligned.m16n8k16.row.col.f32.bf16.bf16.f32 "
        "{%0,%1,%2,%3}, {%4,%5,%6,%7}, {%8,%9}, {%0,%1,%2,%3};"
        : "+f"(d[0]), "+f"(d[1]), "+f"(d[2]), "+f"(d[3])
        : "r"(a[0]), "r"(a[1]), "r"(a[2]), "r"(a[3]), "r"(b.x), "r"(b.y));
}

// ---------------- two-level grid barrier (64 CTAs: 8 groups x 8) ----------
__device__ __forceinline__ void grid_barrier() {
    __syncthreads();
    if (threadIdx.x == 0) {
        __threadfence();
        unsigned gen = *(volatile unsigned*)&g_gen[0];
        unsigned grp = (unsigned)blockIdx.x >> 3;
        if (atomicAdd(&g_gcnt[grp * 32], 1u) == 7u) {
            *(volatile unsigned*)&g_gcnt[grp * 32] = 0u;
            __threadfence();
            if (atomicAdd(&g_root[0], 1u) == 7u) {
                *(volatile unsigned*)&g_root[0] = 0u;
                __threadfence();
                atomicExch(&g_gen[0], gen + 1u);
            }
        }
        while (*(volatile unsigned*)&g_gen[0] == gen) { }
        __threadfence();
    }
    __syncthreads();
}

// ---------------- setup kernels ----------------
__global__ __launch_bounds__(256) void build_tok(const int* __restrict__ X,
                                                 const int* __restrict__ y) {
    int i = blockIdx.x * blockDim.x + threadIdx.x;
    if (i < SSZ * BSZ) {
        int t = i >> 6, b = i & 63;
        g_tok_enc[i] = X[b * SSZ + t];
    }
    if (i < TSZ * BSZ) {
        int t = i >> 6, b = i & 63;
        g_tok_dec[i] = (t == 0) ? BOS : y[b * TSZ + (t - 1)];
    }
}

__global__ __launch_bounds__(256) void zero_hf() {
    int i = blockIdx.x * blockDim.x + threadIdx.x;   // 128 blocks x 256
    if (i < 2 * 16384) {
        ((uint32_t*)g_hf0)[i] = 0u;
        ((uint32_t*)g_hf1)[i] = 0u;
    }
    if (i < 8 * 32) g_gcnt[i] = 0u;
    if (i < 32) { g_root[i] = 0u; g_gen[i] = 0u; }
}

// one-time weight pack into A-fragment order (bf16x2) — unchanged layouts
__global__ __launch_bounds__(256) void pack_w(
    const float* __restrict__ enc_Wih, const float* __restrict__ enc_Whh,
    const float* __restrict__ dec_Wih, const float* __restrict__ dec_Whh) {
    const size_t LW = (size_t)2048 * 512;
    int idx = blockIdx.x * 256 + threadIdx.x;
    if (idx < (1 << 20)) {          // L0: Whh layer0, 32 tiles x (4mt x 32kt)
        int reg = idx & 3, lane = (idx >> 2) & 31, kt = (idx >> 7) & 31;
        int mt = (idx >> 12) & 3, cta = (idx >> 14) & 31, ph = (idx >> 19) & 1;
        int lr = mt * 16 + (lane >> 2) + (reg & 1) * 8;
        int j = cta * 16 + (lr >> 2);
        int g = lr & 3;
        int k = kt * 16 + (lane & 3) * 2 + (reg >> 1) * 8;
        const float* W = ph ? dec_Whh : enc_Whh;
        const float* row = W + (size_t)(g * 512 + j) * 512;
        __nv_bfloat162 p = __floats2bfloat162_rn(row[k], row[k + 1]);
        g_w0f[ph][cta][((mt * 32 + kt) * 32 + lane) * 4 + reg] = *(uint32_t*)&p;
        return;
    }
    int id2 = idx - (1 << 20);
    if (id2 < (1 << 21)) {          // L1: [Wih1 | Whh1], 64 tiles x (2mt x 64kt)
        int reg = id2 & 3, lane = (id2 >> 2) & 31, kt = (id2 >> 7) & 63;
        int mt = (id2 >> 13) & 1, cta = (id2 >> 14) & 63, ph = (id2 >> 20) & 1;
        int lr = mt * 16 + (lane >> 2) + (reg & 1) * 8;
        int j = cta * 8 + (lr >> 2);
        int g = lr & 3;
        int k = kt * 16 + (lane & 3) * 2 + (reg >> 1) * 8;
        const float* Wih = ph ? dec_Wih : enc_Wih;
        const float* Whh = ph ? dec_Whh : enc_Whh;
        const float* row;
        int kk;
        if (k < 512) { row = Wih + LW + (size_t)(g * 512 + j) * 512; kk = k; }
        else         { row = Whh + LW + (size_t)(g * 512 + j) * 512; kk = k - 512; }
        __nv_bfloat162 p = __floats2bfloat162_rn(row[kk], row[kk + 1]);
        g_w1f[ph][cta][((mt * 64 + kt) * 32 + lane) * 4 + reg] = *(uint32_t*)&p;
    }
}

// ================= precompute layer-0 input projections (known-good) ========
__device__ __forceinline__ void fma2(unsigned long long& d, unsigned long long a,
                                     unsigned long long b) {
    asm("fma.rn.f32x2 %0, %1, %2, %0;" : "+l"(d) : "l"(a), "l"(b));
}
__device__ __forceinline__ float2 unpk(unsigned long long v) {
    float2 r;
    asm("mov.b64 {%0,%1}, %2;" : "=f"(r.x), "=f"(r.y) : "l"(v));
    return r;
}
#define LSTM_INNER(s)                                                     \
    do {                                                                  \
        const float2* aR  = sA[s][b];                                     \
        const float2* wiR = sW[s][jl];                                    \
        const float2* wfR = sW[s][4 + jl];                                \
        const float2* wgR = sW[s][8 + jl];                                \
        const float2* woR = sW[s][12 + jl];                               \
        _Pragma("unroll")                                                 \
        for (int q = 0; q < 32; q += 2) {                                 \
            ulonglong2 av = *(const ulonglong2*)(aR + q);                 \
            ulonglong2 wi = *(const ulonglong2*)(wiR + q);                \
            ulonglong2 wf = *(const ulonglong2*)(wfR + q);                \
            ulonglong2 wg = *(const ulonglong2*)(wgR + q);                \
            ulonglong2 wo = *(const ulonglong2*)(woR + q);                \
            fma2(ai, av.x, wi.x); fma2(ai, av.y, wi.y);                   \
            fma2(af, av.x, wf.x); fma2(af, av.y, wf.y);                   \
            fma2(ag, av.x, wg.x); fma2(ag, av.y, wg.y);                   \
            fma2(ao, av.x, wo.x); fma2(ao, av.y, wo.y);                   \
        }                                                                 \
    } while (0)

__global__ __launch_bounds__(256) void precompute_ih(
    int is_dec, const float* __restrict__ emb, const float* __restrict__ W0,
    const float* __restrict__ bih, const float* __restrict__ bhh) {
    __shared__ float2 sA[2][64][34];
    __shared__ float2 sW[2][16][32];
    __shared__ const float* rowptr[64];

    const int* tok = is_dec ? g_tok_dec : g_tok_enc;
    float4* outp   = is_dec ? g_pih_dec : g_pih_enc;

    int t     = blockIdx.y;
    int tid   = threadIdx.x;
    int b     = tid & 63;
    int jl    = tid >> 6;
    int jbase = blockIdx.x << 2;
    int j     = jbase + jl;

    if (tid < 64) rowptr[tid] = emb + (size_t)tok[t * 64 + tid] * 512;
    __syncthreads();

    int wrow = tid >> 4, wq = tid & 15;
    int wg_ = wrow >> 2, wjl = wrow & 3;
    size_t wOff = ((size_t)(wg_ * 512 + jbase + wjl)) * 512 + wq * 4;
    int rows[4], qs[4];
#pragma unroll
    for (int it = 0; it < 4; ++it) {
        int lin = tid + (it << 8);
        rows[it] = lin >> 4;
        qs[it]   = lin & 15;
    }

    unsigned long long ai = 0, af = 0, ag = 0, ao = 0;
    float4 rW, rA[4];

    rW = *(const float4*)(W0 + wOff);
#pragma unroll
    for (int it = 0; it < 4; ++it)
        rA[it] = *(const float4*)(rowptr[rows[it]] + qs[it] * 4);
    *(float4*)&sW[0][wrow][wq * 2] = rW;
#pragma unroll
    for (int it = 0; it < 4; ++it)
        *(float4*)&sA[0][rows[it]][qs[it] * 2] = rA[it];
    __syncthreads();

    for (int c = 0; c < 8; ++c) {
        int s = c & 1;
        bool more = (c + 1 < 8);
        if (more) {
            int k0 = (c + 1) << 6;
            rW = *(const float4*)(W0 + wOff + k0);
#pragma unroll
            for (int it = 0; it < 4; ++it)
                rA[it] = *(const float4*)(rowptr[rows[it]] + k0 + qs[it] * 4);
        }
        LSTM_INNER(s);
        __syncthreads();
        if (more) {
            int nb = (c + 1) & 1;
            *(float4*)&sW[nb][wrow][wq * 2] = rW;
#pragma unroll
            for (int it = 0; it < 4; ++it)
                *(float4*)&sA[nb][rows[it]][qs[it] * 2] = rA[it];
        }
        __syncthreads();
    }

    float2 vi = unpk(ai), vf = unpk(af), vg = unpk(ag), vo = unpk(ao);
    float4 r;
    r.x = vi.x + vi.y + bih[j]        + bhh[j];
    r.y = vf.x + vf.y + bih[512 + j]  + bhh[512 + j];
    r.z = vg.x + vg.y + bih[1024 + j] + bhh[1024 + j];
    r.w = vo.x + vo.y + bih[1536 + j] + bhh[1536 + j];
    outp[((size_t)t * 512 + j) * 64 + b] = r;
}

// ================= persistent mma.sync megakernel (single group) ============
// 64 CTAs; CTA m owns 8 L0 cells AND 8 L1 cells (j in [8m,8m+8)).
// Superstep s: L1(s-1) then L0(s); ONE barrier. Warp w = k-slice kq (8-way).
// B staged by bulk-copy (h0 + h1, 64KB each); A streamed from L2 per kt.
// smem: mbars | sB0 64K | sB1 64K | sD 8x32x72 f32 | sH 2K | sC0 2K | sC1 2K
#define OFF_B0 1024
#define OFF_B1 (OFF_B0 + 65536)
#define OFF_D  (OFF_B1 + 65536)
#define OFF_SH (OFF_D + 73728)
#define OFF_C0 (OFF_SH + 2048)
#define OFF_C1 (OFF_C0 + 2048)
#define MEGA_SMEM (OFF_C1 + 2048)

__global__ __launch_bounds__(256, 1) void mega_mma(
    const float* __restrict__ enc_bih, const float* __restrict__ enc_bhh,
    const float* __restrict__ dec_bih, const float* __restrict__ dec_bhh) {
    extern __shared__ __align__(1024) unsigned char smraw[];
    uint32_t sbase = smem_u32(smraw);
    float* sD  = (float*)(smraw + OFF_D);
    float* sH  = (float*)(smraw + OFF_SH);
    float* sC0 = (float*)(smraw + OFF_C0);
    float* sC1 = (float*)(smraw + OFF_C1);
    const uint2* sB0 = (const uint2*)(smraw + OFF_B0);
    const uint2* sB1 = (const uint2*)(smraw + OFF_B1);

    int tid = threadIdx.x, lane = tid & 31, w = tid >> 5;
    int m = blockIdx.x;
    int kq = w;

    uint32_t mb0 = sbase, mb1 = sbase + 8;
    if (tid == 0) { MBAR_INIT(mb0, 1); MBAR_INIT(mb1, 1); }
    for (int i = tid; i < 512; i += 256) { sC0[i] = 0.f; sC1[i] = 0.f; }
    __syncthreads();

    int jl2 = (tid * 2) >> 6;           // 0..7 local cell for epilogues
    int j_ep = m * 8 + jl2;
    // publish mapping (both layers): this CTA owns kt=m>>1, reg=m&1
    int pnt = tid >> 5, pln = tid & 31;
    int prg = m & 1, pkt = m >> 1;
    int pjloc = (pln & 3) * 2;
    int pb = pnt * 8 + (pln >> 2);
    int pword = ((pkt * 8 + pnt) * 32 + pln) * 2 + prg;

    float bias1[4] = {0.f, 0.f, 0.f, 0.f};
    int ph0 = 0, ph1 = 0;

#pragma unroll 1
    for (int s = 0; s < NSTEPS; ++s) {
        bool a0 = (s < 288), a1 = (s >= 1);

        // issue B copies
        if (w == 0 && elect_one()) {
            MBAR_EXPECT_TX(mb0, 65536u);
#pragma unroll
            for (int c = 0; c < 4; ++c)
                bulk_g2s(sbase + OFF_B0 + c * 16384,
                         g_hf0[(s + 1) & 1] + c * 4096, 16384u, mb0);
            if (a1) {
                MBAR_EXPECT_TX(mb1, 65536u);
#pragma unroll
                for (int c = 0; c < 4; ++c)
                    bulk_g2s(sbase + OFF_B1 + c * 16384,
                             g_hf1[s & 1] + c * 4096, 16384u, mb1);
            }
        }

        // prefetch pih (DRAM) early; consumed in L0 epilogue
        float4 pz[2];
        if (a0) {
            const float4* pihp = (s < 256) ? g_pih_enc : g_pih_dec;
            int t0 = (s < 256) ? s : s - 256;
#pragma unroll
            for (int i = 0; i < 2; ++i)
                pz[i] = pihp[((size_t)t0 * 512 + j_ep) * 64 + ((tid * 2 + i) & 63)];
        }
        if (s == 1 || s == 257) {
            const float* bi = (s == 257) ? dec_bih : enc_bih;
            const float* bh = (s == 257) ? dec_bhh : enc_bhh;
#pragma unroll
            for (int g = 0; g < 4; ++g)
                bias1[g] = bi[2048 + g * 512 + j_ep] + bh[2048 + g * 512 + j_ep];
        }

        MBAR_WAIT(mb0, ph0); ph0 ^= 1;
        if (a1) { MBAR_WAIT(mb1, ph1); ph1 ^= 1; }

        // ---------------- L1(s-1) pass ----------------
        if (a1) {
            int phw = (s >= 257);
            const uint4* asrc = (const uint4*)g_w1f[phw][m];
            float acc[2][8][4];
#pragma unroll
            for (int a = 0; a < 2; ++a)
#pragma unroll
                for (int n = 0; n < 8; ++n)
#pragma unroll
                    for (int r = 0; r < 4; ++r) acc[a][n][r] = 0.f;
#pragma unroll
            for (int kt = 0; kt < 8; ++kt) {
                int ktg = kq * 8 + kt;
                uint32_t A0[4], A1[4];
                *(uint4*)A0 = asrc[(ktg) * 32 + lane];
                *(uint4*)A1 = asrc[(64 + ktg) * 32 + lane];
                const uint2* bs = (ktg < 32) ? (sB0 + (ktg * 8) * 32)
                                             : (sB1 + ((ktg - 32) * 8) * 32);
#pragma unroll
                for (int nt = 0; nt < 8; ++nt) {
                    uint2 bv = bs[nt * 32 + lane];
                    mma_bf16(acc[0][nt], A0, bv);
                    mma_bf16(acc[1][nt], A1, bv);
                }
            }
#pragma unroll
            for (int mt = 0; mt < 2; ++mt) {
                int r1 = mt * 16 + (lane >> 2);
#pragma unroll
                for (int nt = 0; nt < 8; ++nt) {
                    int n1 = nt * 8 + (lane & 3) * 2;
                    *(float2*)&sD[(kq * 32 + r1) * 72 + n1] =
                        make_float2(acc[mt][nt][0], acc[mt][nt][1]);
                    *(float2*)&sD[(kq * 32 + r1 + 8) * 72 + n1] =
                        make_float2(acc[mt][nt][2], acc[mt][nt][3]);
                }
            }
            __syncthreads();
#pragma unroll
            for (int i = 0; i < 2; ++i) {
                int b = (tid * 2 + i) & 63;
                float gv[4];
#pragma unroll
                for (int g = 0; g < 4; ++g) {
                    int r = jl2 * 4 + g;
                    float sum = bias1[g];
#pragma unroll
                    for (int q = 0; q < 8; ++q)
                        sum += sD[(q * 32 + r) * 72 + b];
                    gv[g] = sum;
                }
                float I = sig_ap(gv[0]);
                float F = sig_ap(gv[1]);
                float G = tanh_ap(gv[2]);
                float O = sig_ap(gv[3]);
                float cc = F * sC1[jl2 * 64 + b] + I * G;
                float hh = O * tanh_ap(cc);
                sC1[jl2 * 64 + b] = cc;
                sH[jl2 * 64 + b] = hh;
                if (s == 288) g_h1f[b * 512 + j_ep] = hh;
            }
            __syncthreads();
            {   // publish h1(s-1) -> buf (s-1)&1
                __nv_bfloat162 p = __floats2bfloat162_rn(
                    sH[pjloc * 64 + pb], sH[(pjloc + 1) * 64 + pb]);
                g_hf1[(s + 1) & 1][pword] = *(uint32_t*)&p;
            }
        }

        // ---------------- L0(s) pass ----------------
        if (a0) {
            int phw = (s >= 256);
            const uint4* asrc = (const uint4*)g_w0f[phw][m >> 1];
            int mtoff = (m & 1) * 2;
            float acc[2][8][4];
#pragma unroll
            for (int a = 0; a < 2; ++a)
#pragma unroll
                for (int n = 0; n < 8; ++n)
#pragma unroll
                    for (int r = 0; r < 4; ++r) acc[a][n][r] = 0.f;
#pragma unroll
            for (int kt = 0; kt < 4; ++kt) {
                int ktg = kq * 4 + kt;
                uint32_t A0[4], A1[4];
                *(uint4*)A0 = asrc[((mtoff + 0) * 32 + ktg) * 32 + lane];
                *(uint4*)A1 = asrc[((mtoff + 1) * 32 + ktg) * 32 + lane];
                const uint2* bs = sB0 + (ktg * 8) * 32;
#pragma unroll
                for (int nt = 0; nt < 8; ++nt) {
                    uint2 bv = bs[nt * 32 + lane];
                    mma_bf16(acc[0][nt], A0, bv);
                    mma_bf16(acc[1][nt], A1, bv);
                }
            }
            __syncthreads();   // L1 epilogue sD reads done (when a1)
#pragma unroll
            for (int mt = 0; mt < 2; ++mt) {
                int r1 = mt * 16 + (lane >> 2);
#pragma unroll
                for (int nt = 0; nt < 8; ++nt) {
                    int n1 = nt * 8 + (lane & 3) * 2;
                    *(float2*)&sD[(kq * 32 + r1) * 72 + n1] =
                        make_float2(acc[mt][nt][0], acc[mt][nt][1]);
                    *(float2*)&sD[(kq * 32 + r1 + 8) * 72 + n1] =
                        make_float2(acc[mt][nt][2], acc[mt][nt][3]);
                }
            }
            __syncthreads();
#pragma unroll
            for (int i = 0; i < 2; ++i) {
                int b = (tid * 2 + i) & 63;
                float gv[4] = {
                    (i == 0 ? pz[0].x : pz[1].x), (i == 0 ? pz[0].y : pz[1].y),
                    (i == 0 ? pz[0].z : pz[1].z), (i == 0 ? pz[0].w : pz[1].w)};
#pragma unroll
                for (int g = 0; g < 4; ++g) {
                    int r = jl2 * 4 + g;
                    float sum = 0.f;
#pragma unroll
                    for (int q = 0; q < 8; ++q)
                        sum += sD[(q * 32 + r) * 72 + b];
                    gv[g] += sum;
                }
                float I = sig_ap(gv[0]);
                float F = sig_ap(gv[1]);
                float G = tanh_ap(gv[2]);
                float O = sig_ap(gv[3]);
                float cc = F * sC0[jl2 * 64 + b] + I * G;
                float hh = O * tanh_ap(cc);
                sC0[jl2 * 64 + b] = cc;
                sH[jl2 * 64 + b] = hh;
            }
            __syncthreads();
            {   // publish h0(s) -> buf s&1
                __nv_bfloat162 p = __floats2bfloat162_rn(
                    sH[pjloc * 64 + pb], sH[(pjloc + 1) * 64 + pb]);
                g_hf0[s & 1][pword] = *(uint32_t*)&p;
            }
        }

        grid_barrier();
    }
}

// ---------------- final FC: logits = h_top @ fcW^T + fcb ----------------
__global__ __launch_bounds__(256) void fc_kernel(
    const float* __restrict__ W, const float* __restrict__ bias,
    float* __restrict__ out) {
    __shared__ float sh[64 * 128];
    const float* h = g_h1f;

    int tid = threadIdx.x;
    int nl  = tid & 63;
    int bs  = tid >> 6;
    int n   = blockIdx.x * 64 + nl;

    float acc[16];
#pragma unroll
    for (int i = 0; i < 16; ++i) acc[i] = 0.f;

    for (int c = 0; c < 4; ++c) {
#pragma unroll
        for (int it = 0; it < 8; ++it) {
            int lin = tid + it * 256;
            int row = lin >> 5;
            int kq  = lin & 31;
            *(float4*)&sh[row * 128 + kq * 4] =
                *(const float4*)(h + (size_t)row * 512 + c * 128 + kq * 4);
        }
        __syncthreads();
        const float4* wr = (const float4*)(W + (size_t)n * 512 + c * 128);
#pragma unroll 4
        for (int k4 = 0; k4 < 32; ++k4) {
            float4 wv = wr[k4];
#pragma unroll
            for (int i = 0; i < 16; ++i) {
                int row = bs * 16 + i;
                float4 hv = *(const float4*)&sh[row * 128 + k4 * 4];
                acc[i] += wv.x * hv.x + wv.y * hv.y + wv.z * hv.z + wv.w * hv.w;
            }
        }
        __syncthreads();
    }
    float bb = bias[n];
#pragma unroll
    for (int i = 0; i < 16; ++i) {
        int row = bs * 16 + i;
        out[(size_t)row * VT + n] = acc[i] + bb;
    }
}

// ---------------- in-place log_softmax ----------------
__global__ __launch_bounds__(256) void log_softmax_kernel(float* __restrict__ out) {
    int r = blockIdx.x;
    float* row = out + (size_t)r * VT;
    __shared__ float red[256];
    int tid = threadIdx.x;

    float mx = -1e30f;
    for (int i = tid; i < VT; i += 256) mx = fmaxf(mx, row[i]);
    red[tid] = mx;
    __syncthreads();
    for (int s = 128; s > 0; s >>= 1) {
        if (tid < s) red[tid] = fmaxf(red[tid], red[tid + s]);
        __syncthreads();
    }
    mx = red[0];
    __syncthreads();

    float sum = 0.f;
    for (int i = tid; i < VT; i += 256) sum += expf(row[i] - mx);
    red[tid] = sum;
    __syncthreads();
    for (int s = 128; s > 0; s >>= 1) {
        if (tid < s) red[tid] += red[tid + s];
        __syncthreads();
    }
    float lse = mx + logf(red[0]);
    __syncthreads();

    for (int i = tid; i < VT; i += 256) row[i] = row[i] - lse;
}

// ---------------- host driver (graph-capturable) ----------------
extern "C" void kernel_launch(void* const* d_in, const int* in_sizes, int n_in,
                              void* d_out, int out_size) {
    (void)in_sizes; (void)n_in; (void)out_size;
    const int*   X       = (const int*)d_in[0];
    const int*   y       = (const int*)d_in[1];
    const float* emb_src = (const float*)d_in[2];
    const float* emb_tgt = (const float*)d_in[3];
    const float* enc_Wih = (const float*)d_in[4];
    const float* enc_Whh = (const float*)d_in[5];
    const float* enc_bih = (const float*)d_in[6];
    const float* enc_bhh = (const float*)d_in[7];
    const float* dec_Wih = (const float*)d_in[8];
    const float* dec_Whh = (const float*)d_in[9];
    const float* dec_bih = (const float*)d_in[10];
    const float* dec_bhh = (const float*)d_in[11];
    const float* fcW     = (const float*)d_in[12];
    const float* fcb     = (const float*)d_in[13];
    float* out = (float*)d_out;

    cudaFuncSetAttribute(mega_mma, cudaFuncAttributeMaxDynamicSharedMemorySize,
                         MEGA_SMEM);

    build_tok<<<64, 256>>>(X, y);
    zero_hf<<<128, 256>>>();
    pack_w<<<12288, 256>>>(enc_Wih, enc_Whh, dec_Wih, dec_Whh);

    precompute_ih<<<dim3(128, SSZ), 256>>>(0, emb_src, enc_Wih, enc_bih, enc_bhh);
    precompute_ih<<<dim3(128, TSZ), 256>>>(1, emb_tgt, dec_Wih, dec_bih, dec_bhh);

    mega_mma<<<NBLK, 256, MEGA_SMEM>>>(enc_bih, enc_bhh, dec_bih, dec_bhh);

    fc_kernel<<<500, 256>>>(fcW, fcb, out);
    log_softmax_kernel<<<64, 256>>>(out);
}

// round 15
// speedup vs baseline: 1.2063x; 1.2063x over previous
#include <cuda_runtime.h>
#include <cuda_bf16.h>
#include <cstdint>
#include <cstddef>

// ---------------- problem constants ----------------
#define BSZ   64
#define SSZ   256
#define TSZ   32
#define VT    32000
#define BOS   2
#define NBLK  96
#define NSTEPS 289

// ---------------- device scratch (static; no allocs) ----------------
__device__ float4 g_pih_enc[(size_t)SSZ * 512 * BSZ]; // [t][j][b] (i,f,g,o)
__device__ float4 g_pih_dec[(size_t)TSZ * 512 * BSZ];

// Weights pre-packed in mma A-fragment order, bf16x2 words.
__device__ __align__(128) uint32_t g_w0f[2][32][16384]; // [ph][cta] M=64,K=512
__device__ __align__(128) uint32_t g_w1f[2][64][16384]; // [ph][cta] M=32,K=1024

// h in mma B-fragment order: word ((kt*8+nt)*32+lane)*2+reg
__device__ __align__(128) uint32_t g_hf0[4][16384];     // h layer0, 4-deep
__device__ __align__(128) uint32_t g_hf1[2][16384];     // h layer1, parity
__device__ float g_h1f[BSZ * 512];                      // fp32 h1(final) for FC

__device__ int g_tok_enc[SSZ * BSZ];
__device__ int g_tok_dec[TSZ * BSZ];

__device__ unsigned g_l0_done;
__device__ unsigned g_l1_done;
__device__ unsigned g_gcnt[2 * 32];
__device__ unsigned g_ggen[2 * 32];

// ---------------- helpers ----------------
__device__ __forceinline__ uint32_t smem_u32(const void* p) {
    uint32_t a;
    asm("{ .reg .u64 t; cvta.to.shared.u64 t, %1; cvt.u32.u64 %0, t; }"
        : "=r"(a) : "l"(p));
    return a;
}
__device__ __forceinline__ uint32_t elect_one() {
    uint32_t pred;
    asm volatile("{\n\t.reg .pred p;\n\telect.sync _|p, 0xFFFFFFFF;\n\t"
                 "selp.b32 %0, 1, 0, p;\n\t}" : "=r"(pred));
    return pred;
}
__device__ __forceinline__ float tanh_ap(float x) {
    float y;
    asm("tanh.approx.f32 %0, %1;" : "=f"(y) : "f"(x));
    return y;
}
__device__ __forceinline__ float sig_ap(float x) {
    return 0.5f * tanh_ap(0.5f * x) + 0.5f;
}

#define MBAR_INIT(a, n) \
    asm volatile("mbarrier.init.shared.b64 [%0], %1;" :: "r"(a), "r"(n) : "memory")
#define MBAR_EXPECT_TX(a, n) \
    asm volatile("mbarrier.arrive.expect_tx.shared.b64 _, [%0], %1;" \
                 :: "r"(a), "r"(n) : "memory")
#define MBAR_WAIT(a, ph) \
    asm volatile("{\n\t.reg .pred P1;\n\t" \
        "WL_%=:\n\t" \
        "mbarrier.try_wait.parity.acquire.cta.shared::cta.b64 P1, [%0], %1, 0x989680;\n\t" \
        "@P1 bra.uni WD_%=;\n\t" \
        "bra.uni WL_%=;\n\t" \
        "WD_%=:\n\t}" \
        :: "r"((uint32_t)(a)), "r"((uint32_t)(ph)) : "memory")

__device__ __forceinline__ void bulk_g2s(uint32_t dst, const void* src,
                                         uint32_t bytes, uint32_t mbar) {
    asm volatile(
        "cp.async.bulk.shared::cta.global.mbarrier::complete_tx::bytes [%0], [%1], %2, [%3];"
        :: "r"(dst), "l"(src), "r"(bytes), "r"(mbar) : "memory");
}

// bf16 mma: D[16x8] += A[16x16] * B[16x8], row.col, f32 accum
__device__ __forceinline__ void mma_bf16(float* d, const uint32_t* a, uint2 b) {
    asm volatile(
        "mma.sync.aligned.m16n8k16.row.col.f32.bf16.bf16.f32 "
        "{%0,%1,%2,%3}, {%4,%5,%6,%7}, {%8,%9}, {%0,%1,%2,%3};"
        : "+f"(d[0]), "+f"(d[1]), "+f"(d[2]), "+f"(d[3])
        : "r"(a[0]), "r"(a[1]), "r"(a[2]), "r"(a[3]), "r"(b.x), "r"(b.y));
}

// ---------------- per-group barrier ----------------
__device__ __forceinline__ void group_barrier(int grp, unsigned n) {
    __syncthreads();
    if (threadIdx.x == 0) {
        __threadfence();
        unsigned gen = *(volatile unsigned*)&g_ggen[grp * 32];
        if (atomicAdd(&g_gcnt[grp * 32], 1u) == n - 1u) {
            *(volatile unsigned*)&g_gcnt[grp * 32] = 0u;
            __threadfence();
            atomicExch(&g_ggen[grp * 32], gen + 1u);
        } else {
            while (*(volatile unsigned*)&g_ggen[grp * 32] == gen) { }
        }
        __threadfence();
    }
    __syncthreads();
}

// ---------------- setup kernels ----------------
__global__ __launch_bounds__(256) void build_tok(const int* __restrict__ X,
                                                 const int* __restrict__ y) {
    int i = blockIdx.x * blockDim.x + threadIdx.x;
    if (i < SSZ * BSZ) {
        int t = i >> 6, b = i & 63;
        g_tok_enc[i] = X[b * SSZ + t];
    }
    if (i < TSZ * BSZ) {
        int t = i >> 6, b = i & 63;
        g_tok_dec[i] = (t == 0) ? BOS : y[b * TSZ + (t - 1)];
    }
}

__global__ __launch_bounds__(256) void zero_hf() {
    int i = blockIdx.x * blockDim.x + threadIdx.x;   // 256 blocks
    if (i < 4 * 16384) ((uint32_t*)g_hf0)[i] = 0u;
    if (i < 2 * 16384) ((uint32_t*)g_hf1)[i] = 0u;
    if (i == 0) { g_l0_done = 0u; g_l1_done = 0u; }
}

// one-time weight pack into A-fragment order (bf16x2)
__global__ __launch_bounds__(256) void pack_w(
    const float* __restrict__ enc_Wih, const float* __restrict__ enc_Whh,
    const float* __restrict__ dec_Wih, const float* __restrict__ dec_Whh) {
    const size_t LW = (size_t)2048 * 512;
    int idx = blockIdx.x * 256 + threadIdx.x;
    if (idx < (1 << 20)) {          // L0: Whh layer0, 32 ctas x (4mt x 32kt)
        int reg = idx & 3, lane = (idx >> 2) & 31, kt = (idx >> 7) & 31;
        int mt = (idx >> 12) & 3, cta = (idx >> 14) & 31, ph = (idx >> 19) & 1;
        int lr = mt * 16 + (lane >> 2) + (reg & 1) * 8;
        int j = cta * 16 + (lr >> 2);
        int g = lr & 3;
        int k = kt * 16 + (lane & 3) * 2 + (reg >> 1) * 8;
        const float* W = ph ? dec_Whh : enc_Whh;
        const float* row = W + (size_t)(g * 512 + j) * 512;
        __nv_bfloat162 p = __floats2bfloat162_rn(row[k], row[k + 1]);
        g_w0f[ph][cta][((mt * 32 + kt) * 32 + lane) * 4 + reg] = *(uint32_t*)&p;
        return;
    }
    int id2 = idx - (1 << 20);
    if (id2 < (1 << 21)) {          // L1: [Wih1 | Whh1], 64 ctas x (2mt x 64kt)
        int reg = id2 & 3, lane = (id2 >> 2) & 31, kt = (id2 >> 7) & 63;
        int mt = (id2 >> 13) & 1, cta = (id2 >> 14) & 63, ph = (id2 >> 20) & 1;
        int lr = mt * 16 + (lane >> 2) + (reg & 1) * 8;
        int j = cta * 8 + (lr >> 2);
        int g = lr & 3;
        int k = kt * 16 + (lane & 3) * 2 + (reg >> 1) * 8;
        const float* Wih = ph ? dec_Wih : enc_Wih;
        const float* Whh = ph ? dec_Whh : enc_Whh;
        const float* row;
        int kk;
        if (k < 512) { row = Wih + LW + (size_t)(g * 512 + j) * 512; kk = k; }
        else         { row = Whh + LW + (size_t)(g * 512 + j) * 512; kk = k - 512; }
        __nv_bfloat162 p = __floats2bfloat162_rn(row[kk], row[kk + 1]);
        g_w1f[ph][cta][((mt * 64 + kt) * 32 + lane) * 4 + reg] = *(uint32_t*)&p;
    }
}

// ================= precompute layer-0 input projections (known-good) ========
__device__ __forceinline__ void fma2(unsigned long long& d, unsigned long long a,
                                     unsigned long long b) {
    asm("fma.rn.f32x2 %0, %1, %2, %0;" : "+l"(d) : "l"(a), "l"(b));
}
__device__ __forceinline__ float2 unpk(unsigned long long v) {
    float2 r;
    asm("mov.b64 {%0,%1}, %2;" : "=f"(r.x), "=f"(r.y) : "l"(v));
    return r;
}
#define LSTM_INNER(s)                                                     \
    do {                                                                  \
        const float2* aR  = sA[s][b];                                     \
        const float2* wiR = sW[s][jl];                                    \
        const float2* wfR = sW[s][4 + jl];                                \
        const float2* wgR = sW[s][8 + jl];                                \
        const float2* woR = sW[s][12 + jl];                               \
        _Pragma("unroll")                                                 \
        for (int q = 0; q < 32; q += 2) {                                 \
            ulonglong2 av = *(const ulonglong2*)(aR + q);                 \
            ulonglong2 wi = *(const ulonglong2*)(wiR + q);                \
            ulonglong2 wf = *(const ulonglong2*)(wfR + q);                \
            ulonglong2 wg = *(const ulonglong2*)(wgR + q);                \
            ulonglong2 wo = *(const ulonglong2*)(woR + q);                \
            fma2(ai, av.x, wi.x); fma2(ai, av.y, wi.y);                   \
            fma2(af, av.x, wf.x); fma2(af, av.y, wf.y);                   \
            fma2(ag, av.x, wg.x); fma2(ag, av.y, wg.y);                   \
            fma2(ao, av.x, wo.x); fma2(ao, av.y, wo.y);                   \
        }                                                                 \
    } while (0)

__global__ __launch_bounds__(256) void precompute_ih(
    int is_dec, const float* __restrict__ emb, const float* __restrict__ W0,
    const float* __restrict__ bih, const float* __restrict__ bhh) {
    __shared__ float2 sA[2][64][34];
    __shared__ float2 sW[2][16][32];
    __shared__ const float* rowptr[64];

    const int* tok = is_dec ? g_tok_dec : g_tok_enc;
    float4* outp   = is_dec ? g_pih_dec : g_pih_enc;

    int t     = blockIdx.y;
    int tid   = threadIdx.x;
    int b     = tid & 63;
    int jl    = tid >> 6;
    int jbase = blockIdx.x << 2;
    int j     = jbase + jl;

    if (tid < 64) rowptr[tid] = emb + (size_t)tok[t * 64 + tid] * 512;
    __syncthreads();

    int wrow = tid >> 4, wq = tid & 15;
    int wg_ = wrow >> 2, wjl = wrow & 3;
    size_t wOff = ((size_t)(wg_ * 512 + jbase + wjl)) * 512 + wq * 4;
    int rows[4], qs[4];
#pragma unroll
    for (int it = 0; it < 4; ++it) {
        int lin = tid + (it << 8);
        rows[it] = lin >> 4;
        qs[it]   = lin & 15;
    }

    unsigned long long ai = 0, af = 0, ag = 0, ao = 0;
    float4 rW, rA[4];

    rW = *(const float4*)(W0 + wOff);
#pragma unroll
    for (int it = 0; it < 4; ++it)
        rA[it] = *(const float4*)(rowptr[rows[it]] + qs[it] * 4);
    *(float4*)&sW[0][wrow][wq * 2] = rW;
#pragma unroll
    for (int it = 0; it < 4; ++it)
        *(float4*)&sA[0][rows[it]][qs[it] * 2] = rA[it];
    __syncthreads();

    for (int c = 0; c < 8; ++c) {
        int s = c & 1;
        bool more = (c + 1 < 8);
        if (more) {
            int k0 = (c + 1) << 6;
            rW = *(const float4*)(W0 + wOff + k0);
#pragma unroll
            for (int it = 0; it < 4; ++it)
                rA[it] = *(const float4*)(rowptr[rows[it]] + k0 + qs[it] * 4);
        }
        LSTM_INNER(s);
        __syncthreads();
        if (more) {
            int nb = (c + 1) & 1;
            *(float4*)&sW[nb][wrow][wq * 2] = rW;
#pragma unroll
            for (int it = 0; it < 4; ++it)
                *(float4*)&sA[nb][rows[it]][qs[it] * 2] = rA[it];
        }
        __syncthreads();
    }

    float2 vi = unpk(ai), vf = unpk(af), vg = unpk(ag), vo = unpk(ao);
    float4 r;
    r.x = vi.x + vi.y + bih[j]        + bhh[j];
    r.y = vf.x + vf.y + bih[512 + j]  + bhh[512 + j];
    r.z = vg.x + vg.y + bih[1024 + j] + bhh[1024 + j];
    r.w = vo.x + vo.y + bih[1536 + j] + bhh[1536 + j];
    outp[((size_t)t * 512 + j) * 64 + b] = r;
}

// ================= persistent mma.sync megakernel (R12 + latency trims) =====
// CTA 0-31: L0 (M=64 rows, K=512, 4-way k-split). CTA 32-95: L1 (M=32, K=1024,
// 8-way k-split). A-fragments register-resident; B via bulk-copy. Trims vs
// R12: pih prefetched at step start; own-group copies issued BEFORE
// cross-group polls (only L1's h0 copy stays after its poll).
// smem: [0,1024) mbars | [1024,+128K) B frags | [132096,+72K) sD pitch 72 |
//       [205824,+4K) sH | [209920,+4K) sC
#define OFF_B  1024
#define OFF_D  132096
#define OFF_SH 205824
#define OFF_C  209920
#define MEGA_SMEM 214016

__global__ __launch_bounds__(256, 1) void mega_mma(
    const float* __restrict__ enc_bih, const float* __restrict__ enc_bhh,
    const float* __restrict__ dec_bih, const float* __restrict__ dec_bhh) {
    extern __shared__ __align__(1024) unsigned char smraw[];
    uint32_t sbase = smem_u32(smraw);
    float* sD = (float*)(smraw + OFF_D);
    float* sH = (float*)(smraw + OFF_SH);
    float* sC = (float*)(smraw + OFF_C);
    const uint2* bfr = (const uint2*)(smraw + OFF_B);

    int tid = threadIdx.x, lane = tid & 31, w = tid >> 5;
    int cta = blockIdx.x;
    int isP1 = (cta >= 32);
    int m = isP1 ? cta - 32 : cta;
    const int cells = isP1 ? 8 : 16;
    const int per   = isP1 ? 2 : 4;
    const int NKT   = isP1 ? 64 : 32;
    const int KSP   = isP1 ? 8 : 4;
    const int Mr    = cells * 4;
    const unsigned gn = isP1 ? 64u : 32u;

    int mtA0, kq;
    if (isP1) { mtA0 = 0; kq = w; } else { mtA0 = (w & 1) * 2; kq = w >> 1; }

    int jl = (tid * per) >> 6;
    int j_ep = m * cells + jl;

    if (tid == 0)
        for (int i = 0; i < 8; ++i) MBAR_INIT(sbase + i * 8, 1);
    for (int i = tid; i < cells * 64; i += 256) sC[i] = 0.f;
    __syncthreads();

    uint32_t Afr[2][8][4];
    float bias[4] = {0.f, 0.f, 0.f, 0.f};
    int phB = 0;

#pragma unroll 1
    for (int s = 0; s < NSTEPS; ++s) {
        bool active = isP1 ? (s >= 1) : (s < 288);

        // (re)load A fragments + bias at phase boundaries
        if (s == 0 || (!isP1 && s == 256) || (isP1 && s == 257)) {
            int phw = isP1 ? (s >= 257) : (s >= 256);
            const uint4* asrc = isP1 ? (const uint4*)g_w1f[phw][m]
                                     : (const uint4*)g_w0f[phw][m];
#pragma unroll
            for (int mt = 0; mt < 2; ++mt)
#pragma unroll
                for (int kt = 0; kt < 8; ++kt)
                    *(uint4*)Afr[mt][kt] =
                        asrc[((mtA0 + mt) * NKT + kq * 8 + kt) * 32 + lane];
            if (isP1) {
                const float* bi = phw ? dec_bih : enc_bih;
                const float* bh = phw ? dec_bhh : enc_bhh;
#pragma unroll
                for (int g = 0; g < 4; ++g)
                    bias[g] = bi[2048 + g * 512 + j_ep] +
                              bh[2048 + g * 512 + j_ep];
            }
        }

        int rbuf = (s + 3) & 3;

        // early copies + pih prefetch (own-group / DRAM data, safe pre-poll)
        float4 pz[4];
        if (!isP1 && active) {
            if (w == 0 && elect_one()) {
#pragma unroll
                for (int c = 0; c < 4; ++c) {
                    MBAR_EXPECT_TX(sbase + c * 8, 16384u);
                    bulk_g2s(sbase + OFF_B + c * 16384, g_hf0[rbuf] + c * 4096,
                             16384u, sbase + c * 8);
                }
            }
            const float4* pihp = (s < 256) ? g_pih_enc : g_pih_dec;
            int t0 = (s < 256) ? s : s - 256;
#pragma unroll
            for (int i = 0; i < 4; ++i)
                pz[i] = pihp[((size_t)t0 * 512 + j_ep) * 64 + ((tid * 4 + i) & 63)];
        }
        if (isP1 && active && w == 0 && elect_one()) {
            int hpar = s & 1;
#pragma unroll
            for (int c = 0; c < 4; ++c) {
                MBAR_EXPECT_TX(sbase + (4 + c) * 8, 16384u);
                bulk_g2s(sbase + OFF_B + (4 + c) * 16384,
                         g_hf1[hpar] + c * 4096, 16384u, sbase + (4 + c) * 8);
            }
        }

        // inter-group throttles / polls
        if (!isP1) {
            if (s >= 4) {
                if (tid == 0)
                    while (*(volatile unsigned*)&g_l1_done < (unsigned)(s - 3)) { }
                __syncthreads();
            }
        } else if (active) {
            if (tid == 0)
                while (*(volatile unsigned*)&g_l0_done < (unsigned)s) { }
            __syncthreads();
            // h0 copies only legal after the poll
            if (w == 0 && elect_one()) {
#pragma unroll
                for (int c = 0; c < 4; ++c) {
                    MBAR_EXPECT_TX(sbase + c * 8, 16384u);
                    bulk_g2s(sbase + OFF_B + c * 16384, g_hf0[rbuf] + c * 4096,
                             16384u, sbase + c * 8);
                }
            }
        }

        if (active) {
            int mymb = isP1 ? w : kq;
            MBAR_WAIT(sbase + mymb * 8, phB);

            float acc[2][8][4];
#pragma unroll
            for (int a = 0; a < 2; ++a)
#pragma unroll
                for (int n = 0; n < 8; ++n)
#pragma unroll
                    for (int r = 0; r < 4; ++r) acc[a][n][r] = 0.f;

#pragma unroll
            for (int kt = 0; kt < 8; ++kt) {
                int ktg = kq * 8 + kt;
#pragma unroll
                for (int nt = 0; nt < 8; ++nt) {
                    uint2 bv = bfr[(ktg * 8 + nt) * 32 + lane];
                    mma_bf16(acc[0][nt], Afr[0][kt], bv);
                    mma_bf16(acc[1][nt], Afr[1][kt], bv);
                }
            }

            // partials -> sD[(kq*Mr + r)*72 + n]
#pragma unroll
            for (int mt = 0; mt < 2; ++mt) {
                int r1 = (mtA0 + mt) * 16 + (lane >> 2);
#pragma unroll
                for (int nt = 0; nt < 8; ++nt) {
                    int n1 = nt * 8 + (lane & 3) * 2;
                    *(float2*)&sD[(kq * Mr + r1) * 72 + n1] =
                        make_float2(acc[mt][nt][0], acc[mt][nt][1]);
                    *(float2*)&sD[(kq * Mr + r1 + 8) * 72 + n1] =
                        make_float2(acc[mt][nt][2], acc[mt][nt][3]);
                }
            }
            __syncthreads();

            // fused LSTM cell epilogue
#pragma unroll
            for (int i = 0; i < 4; ++i) {
                if (i >= per) break;
                int b = (tid * per + i) & 63;
                float gv[4];
#pragma unroll
                for (int g = 0; g < 4; ++g) {
                    int r = jl * 4 + g;
                    float sum = 0.f;
                    for (int q = 0; q < KSP; ++q)
                        sum += sD[(q * Mr + r) * 72 + b];
                    gv[g] = sum;
                }
                if (isP1) {
                    gv[0] += bias[0]; gv[1] += bias[1];
                    gv[2] += bias[2]; gv[3] += bias[3];
                } else {
                    gv[0] += pz[i].x; gv[1] += pz[i].y;
                    gv[2] += pz[i].z; gv[3] += pz[i].w;
                }
                float I = sig_ap(gv[0]);
                float F = sig_ap(gv[1]);
                float G = tanh_ap(gv[2]);
                float O = sig_ap(gv[3]);
                float cc = F * sC[jl * 64 + b] + I * G;
                float hh = O * tanh_ap(cc);
                sC[jl * 64 + b] = cc;
                sH[jl * 64 + b] = hh;
                if (isP1 && s == 288) g_h1f[b * 512 + j_ep] = hh;
            }
            __syncthreads();

            // pack h into B-fragment gmem words
            if (!isP1) {
                int wbuf = s & 3;
#pragma unroll
                for (int i = 0; i < 2; ++i) {
                    int wi = tid * 2 + i;
                    int nt = wi >> 6, rem = wi & 63, ln = rem >> 1, rg = rem & 1;
                    int jloc = (ln & 3) * 2 + rg * 8;
                    int b = nt * 8 + (ln >> 2);
                    __nv_bfloat162 p = __floats2bfloat162_rn(
                        sH[jloc * 64 + b], sH[(jloc + 1) * 64 + b]);
                    g_hf0[wbuf][((m * 8 + nt) * 32 + ln) * 2 + rg] =
                        *(uint32_t*)&p;
                }
            } else {
                int outpar = (s & 1) ^ 1;
                int nt = tid >> 5, ln = tid & 31;
                int rg = m & 1, kt = m >> 1;
                int jloc = (ln & 3) * 2;
                int b = nt * 8 + (ln >> 2);
                __nv_bfloat162 p = __floats2bfloat162_rn(
                    sH[jloc * 64 + b], sH[(jloc + 1) * 64 + b]);
                g_hf1[outpar][((kt * 8 + nt) * 32 + ln) * 2 + rg] =
                    *(uint32_t*)&p;
            }
            phB ^= 1;
        }

        group_barrier(isP1, gn);
        if (tid == 0) {
            if (cta == 0)       atomicExch(&g_l0_done, (unsigned)(s + 1));
            else if (cta == 32) atomicExch(&g_l1_done, (unsigned)(s + 1));
        }
    }
}

// ---------------- final FC: logits = h_top @ fcW^T + fcb ----------------
__global__ __launch_bounds__(256) void fc_kernel(
    const float* __restrict__ W, const float* __restrict__ bias,
    float* __restrict__ out) {
    __shared__ float sh[64 * 128];
    const float* h = g_h1f;

    int tid = threadIdx.x;
    int nl  = tid & 63;
    int bs  = tid >> 6;
    int n   = blockIdx.x * 64 + nl;

    float acc[16];
#pragma unroll
    for (int i = 0; i < 16; ++i) acc[i] = 0.f;

    for (int c = 0; c < 4; ++c) {
#pragma unroll
        for (int it = 0; it < 8; ++it) {
            int lin = tid + it * 256;
            int row = lin >> 5;
            int kq  = lin & 31;
            *(float4*)&sh[row * 128 + kq * 4] =
                *(const float4*)(h + (size_t)row * 512 + c * 128 + kq * 4);
        }
        __syncthreads();
        const float4* wr = (const float4*)(W + (size_t)n * 512 + c * 128);
#pragma unroll 4
        for (int k4 = 0; k4 < 32; ++k4) {
            float4 wv = wr[k4];
#pragma unroll
            for (int i = 0; i < 16; ++i) {
                int row = bs * 16 + i;
                float4 hv = *(const float4*)&sh[row * 128 + k4 * 4];
                acc[i] += wv.x * hv.x + wv.y * hv.y + wv.z * hv.z + wv.w * hv.w;
            }
        }
        __syncthreads();
    }
    float bb = bias[n];
#pragma unroll
    for (int i = 0; i < 16; ++i) {
        int row = bs * 16 + i;
        out[(size_t)row * VT + n] = acc[i] + bb;
    }
}

// ---------------- in-place log_softmax ----------------
__global__ __launch_bounds__(256) void log_softmax_kernel(float* __restrict__ out) {
    int r = blockIdx.x;
    float* row = out + (size_t)r * VT;
    __shared__ float red[256];
    int tid = threadIdx.x;

    float mx = -1e30f;
    for (int i = tid; i < VT; i += 256) mx = fmaxf(mx, row[i]);
    red[tid] = mx;
    __syncthreads();
    for (int s = 128; s > 0; s >>= 1) {
        if (tid < s) red[tid] = fmaxf(red[tid], red[tid + s]);
        __syncthreads();
    }
    mx = red[0];
    __syncthreads();

    float sum = 0.f;
    for (int i = tid; i < VT; i += 256) sum += expf(row[i] - mx);
    red[tid] = sum;
    __syncthreads();
    for (int s = 128; s > 0; s >>= 1) {
        if (tid < s) red[tid] += red[tid + s];
        __syncthreads();
    }
    float lse = mx + logf(red[0]);
    __syncthreads();

    for (int i = tid; i < VT; i += 256) row[i] = row[i] - lse;
}

// ---------------- host driver (graph-capturable) ----------------
extern "C" void kernel_launch(void* const* d_in, const int* in_sizes, int n_in,
                              void* d_out, int out_size) {
    (void)in_sizes; (void)n_in; (void)out_size;
    const int*   X       = (const int*)d_in[0];
    const int*   y       = (const int*)d_in[1];
    const float* emb_src = (const float*)d_in[2];
    const float* emb_tgt = (const float*)d_in[3];
    const float* enc_Wih = (const float*)d_in[4];
    const float* enc_Whh = (const float*)d_in[5];
    const float* enc_bih = (const float*)d_in[6];
    const float* enc_bhh = (const float*)d_in[7];
    const float* dec_Wih = (const float*)d_in[8];
    const float* dec_Whh = (const float*)d_in[9];
    const float* dec_bih = (const float*)d_in[10];
    const float* dec_bhh = (const float*)d_in[11];
    const float* fcW     = (const float*)d_in[12];
    const float* fcb     = (const float*)d_in[13];
    float* out = (float*)d_out;

    cudaFuncSetAttribute(mega_mma, cudaFuncAttributeMaxDynamicSharedMemorySize,
                         MEGA_SMEM);

    build_tok<<<64, 256>>>(X, y);
    zero_hf<<<256, 256>>>();
    pack_w<<<12288, 256>>>(enc_Wih, enc_Whh, dec_Wih, dec_Whh);

    precompute_ih<<<dim3(128, SSZ), 256>>>(0, emb_src, enc_Wih, enc_bih, enc_bhh);
    precompute_ih<<<dim3(128, TSZ), 256>>>(1, emb_tgt, dec_Wih, dec_bih, dec_bhh);

    mega_mma<<<NBLK, 256, MEGA_SMEM>>>(enc_bih, enc_bhh, dec_bih, dec_bhh);

    fc_kernel<<<500, 256>>>(fcW, fcb, out);
    log_softmax_kernel<<<64, 256>>>(out);
}